// round 12
// baseline (speedup 1.0000x reference)
#include <cuda_runtime.h>
#include <cuda_fp16.h>
#include <mma.h>
#include <cstdint>

using namespace nvcuda;

#define N_NODES 50000
#define IN_CH   128
#define EDGE_DIM 32
#define CAT_CH  (IN_CH + EDGE_DIM)   // 160
#define OUT_CH  128
#define BUCKET_CAP 128
#define KCHUNKS (CAT_CH / 16)        // 10
#define NTILES  ((N_NODES + 15) / 16)  // 3125

// Static device scratch (no allocations allowed)
// A in fragment-native tiled layout: [tile][k-chunk][16 rows][16 cols] fp16
__device__ __align__(128) __half g_aggtile[(size_t)(NTILES + 8) * KCHUNKS * 256]; // ~16 MB
__device__ __align__(128) __half g_xh[(size_t)N_NODES * IN_CH];             // 12.8 MB
__device__ __align__(128) __half g_wh[CAT_CH * OUT_CH];                     // 40 KB
__device__ __align__(128) float  g_biastile[16 * OUT_CH];                   // 8 KB
__device__ __align__(16)  uint4  g_edges16[(size_t)N_NODES * BUCKET_CAP];   // 102 MB
__device__ int g_count[N_NODES];

// ---------------------------------------------------------------------------
// Kernel 1: prep = zero(count) + x->fp16 + W->fp16 + bias tile
// ---------------------------------------------------------------------------
__global__ void prep_kernel(const float2* __restrict__ x2, int n2,
                            const float2* __restrict__ w2,
                            const float*  __restrict__ b,
                            int N) {
    int i = blockIdx.x * blockDim.x + threadIdx.x;
    int stride = gridDim.x * blockDim.x;

    __half2* xdst = reinterpret_cast<__half2*>(g_xh);
    for (int k = i; k < n2; k += stride) {
        float2 v = __ldg(&x2[k]);
        xdst[k] = __float22half2_rn(v);
    }
    __half2* wdst = reinterpret_cast<__half2*>(g_wh);
    for (int k = i; k < (CAT_CH * OUT_CH) / 2; k += stride) {
        float2 v = __ldg(&w2[k]);
        wdst[k] = __float22half2_rn(v);
    }
    for (int k = i; k < 16 * OUT_CH; k += stride) {
        g_biastile[k] = __ldg(&b[k & (OUT_CH - 1)]);
    }
    for (int k = i; k < N; k += stride) g_count[k] = 0;
}

// ---------------------------------------------------------------------------
// Kernel 2: bucket fill, 16B records {norm, e, col, 0}
// ---------------------------------------------------------------------------
__device__ __forceinline__ void fill_one(int r, int c, float nm, int e) {
    int pos = atomicAdd(&g_count[r], 1);
    if (pos < BUCKET_CAP) {
        g_edges16[(size_t)r * BUCKET_CAP + pos] =
            make_uint4(__float_as_uint(nm), (unsigned)e, (unsigned)c, 0u);
    }
}

__global__ void fill_kernel(const int4*   __restrict__ row4,
                            const int4*   __restrict__ col4,
                            const float4* __restrict__ norm4,
                            int E4,
                            const int* __restrict__ row,
                            const int* __restrict__ col,
                            const float* __restrict__ norm,
                            int E) {
    int i = blockIdx.x * blockDim.x + threadIdx.x;
    if (i < E4) {
        int4   r  = __ldg(&row4[i]);
        int4   c  = __ldg(&col4[i]);
        float4 nm = __ldg(&norm4[i]);
        int e = i * 4;
        fill_one(r.x, c.x, nm.x, e + 0);
        fill_one(r.y, c.y, nm.y, e + 1);
        fill_one(r.z, c.z, nm.z, e + 2);
        fill_one(r.w, c.w, nm.w, e + 3);
    }
    if (i == 0) {
        for (int t = E4 * 4; t < E; t++) fill_one(row[t], col[t], norm[t], t);
    }
}

// ---------------------------------------------------------------------------
// Kernel 3: aggregation. One warp per node; x fp16 gather + ea fp32 gather;
// writes the A row in FRAGMENT-TILED layout:
//   chunk address = ((tile*10 + k)*16 + row_in_tile)*16 + col_in_chunk
// lane l -> x channels [4l,4l+4): k = l>>2, col = (l&3)*4  (one 8B store)
//           edge channel 128+l:   k = 8+(l>>4), col = l&15 (one 2B store)
// ---------------------------------------------------------------------------
__device__ __forceinline__ void acc_half4(float4& acc, uint2 u, float nm) {
    float2 f01 = __half22float2(*reinterpret_cast<__half2*>(&u.x));
    float2 f23 = __half22float2(*reinterpret_cast<__half2*>(&u.y));
    acc.x += nm * f01.x; acc.y += nm * f01.y;
    acc.z += nm * f23.x; acc.w += nm * f23.y;
}

__global__ void aggregate_kernel(const float* __restrict__ ea, int N) {
    int n    = (blockIdx.x * blockDim.x + threadIdx.x) >> 5;
    int lane = threadIdx.x & 31;
    if (n >= N) return;

    int cnt = __ldg(&g_count[n]);
    if (cnt > BUCKET_CAP) cnt = BUCKET_CAP;

    const uint4* bucket = g_edges16 + (size_t)n * BUCKET_CAP;
    const uint2* xh = reinterpret_cast<const uint2*>(g_xh);

    float4 acc = make_float4(0.f, 0.f, 0.f, 0.f);
    float  acce = 0.f;

    int full = cnt & ~7;
    int j = 0;
    for (; j < full; j += 8) {
        uint4 r[8];
        #pragma unroll
        for (int q = 0; q < 8; q++) r[q] = __ldg(&bucket[j + q]);
        uint2 u[8];
        #pragma unroll
        for (int q = 0; q < 8; q++)
            u[q] = __ldg(&xh[r[q].z * (IN_CH / 4) + (unsigned)lane]);
        float g[8];
        #pragma unroll
        for (int q = 0; q < 8; q++)
            g[q] = __ldg(&ea[(size_t)r[q].y * EDGE_DIM + lane]);
        #pragma unroll
        for (int q = 0; q < 8; q++) {
            float w = __uint_as_float(r[q].x);
            acc_half4(acc, u[q], w);
            acce += w * g[q];
        }
    }
    if (j < cnt) {
        uint4 r[8];
        float w[8];
        #pragma unroll
        for (int q = 0; q < 8; q++) {
            int idx  = j + q;
            int slot = (idx < cnt) ? idx : 0;
            r[q] = __ldg(&bucket[slot]);
            w[q] = (idx < cnt) ? __uint_as_float(r[q].x) : 0.f;
        }
        uint2 u[8];
        #pragma unroll
        for (int q = 0; q < 8; q++)
            u[q] = __ldg(&xh[r[q].z * (IN_CH / 4) + (unsigned)lane]);
        float g[8];
        #pragma unroll
        for (int q = 0; q < 8; q++)
            g[q] = __ldg(&ea[(size_t)r[q].y * EDGE_DIM + lane]);
        #pragma unroll
        for (int q = 0; q < 8; q++) {
            acc_half4(acc, u[q], w[q]);
            acce += w[q] * g[q];
        }
    }

    // tiled store
    int t  = n >> 4;
    int rr = n & 15;
    __half* base = g_aggtile + (size_t)t * (KCHUNKS * 256);

    __half2 h01 = __floats2half2_rn(acc.x, acc.y);
    __half2 h23 = __floats2half2_rn(acc.z, acc.w);
    uint2 st;
    st.x = *reinterpret_cast<uint32_t*>(&h01);
    st.y = *reinterpret_cast<uint32_t*>(&h23);
    *reinterpret_cast<uint2*>(base + (lane >> 2) * 256 + rr * 16 + (lane & 3) * 4) = st;

    base[(8 + (lane >> 4)) * 256 + rr * 16 + (lane & 15)] = __float2half_rn(acce);
}

// ---------------------------------------------------------------------------
// Kernel 4: GEMM. W in smem; A fragments from tile-contiguous global (512 B
// per fragment); bias-initialized accumulators; direct store to out.
// ---------------------------------------------------------------------------
#define GEMM_ROWS 64
#define SW_BYTES (CAT_CH * OUT_CH * 2)   // 40960

__global__ void gemm_wmma_kernel(float* __restrict__ out, int N) {
    __shared__ __align__(16) __half sW[CAT_CH * OUT_CH];

    int tid = threadIdx.x;
    {
        const uint4* src = reinterpret_cast<const uint4*>(g_wh);
        uint4* dst = reinterpret_cast<uint4*>(sW);
        #pragma unroll
        for (int i = tid; i < SW_BYTES / 16; i += 256) dst[i] = src[i];
    }
    __syncthreads();

    int wid = tid >> 5;
    int mi = wid & 3;
    int ng = wid >> 2;

    int rowBase = blockIdx.x * GEMM_ROWS + mi * 16;
    if (rowBase >= N) return;            // N % 16 == 0

    int tile = rowBase >> 4;
    const __half* A = g_aggtile + (size_t)tile * (KCHUNKS * 256);
    const __half* Wp = sW + ng * 64;
    float* outp = out + (size_t)rowBase * OUT_CH + ng * 64;

    wmma::fragment<wmma::accumulator, 16, 16, 16, float> acc[4];
    #pragma unroll
    for (int f = 0; f < 4; f++)
        wmma::load_matrix_sync(acc[f], g_biastile + f * 16, OUT_CH, wmma::mem_row_major);

    #pragma unroll
    for (int k = 0; k < KCHUNKS; k++) {
        wmma::fragment<wmma::matrix_a, 16, 16, 16, __half, wmma::row_major> a;
        wmma::load_matrix_sync(a, A + k * 256, 16);   // contiguous 512 B
        #pragma unroll
        for (int f = 0; f < 4; f++) {
            wmma::fragment<wmma::matrix_b, 16, 16, 16, __half, wmma::row_major> bb;
            wmma::load_matrix_sync(bb, Wp + k * 16 * OUT_CH + f * 16, OUT_CH);
            wmma::mma_sync(acc[f], a, bb, acc[f]);
        }
    }

    #pragma unroll
    for (int f = 0; f < 4; f++)
        wmma::store_matrix_sync(outp + f * 16, acc[f], OUT_CH, wmma::mem_row_major);
}

// ---------------------------------------------------------------------------
// Launch: 4 kernels, single stream. (4th = gemm = profiled slot)
// ---------------------------------------------------------------------------
extern "C" void kernel_launch(void* const* d_in, const int* in_sizes, int n_in,
                              void* d_out, int out_size) {
    const float* x         = (const float*)d_in[0];
    const int*   row       = (const int*)  d_in[1];
    const int*   col       = (const int*)  d_in[2];
    const float* norm      = (const float*)d_in[3];
    const float* edge_attr = (const float*)d_in[4];
    const float* W         = (const float*)d_in[5];
    const float* b         = (const float*)d_in[6];
    float* out = (float*)d_out;

    int N = in_sizes[0] / IN_CH;
    int E = in_sizes[1];
    int E4 = E / 4;

    // 1) prep
    prep_kernel<<<2048, 512>>>(reinterpret_cast<const float2*>(x),
                               (N * IN_CH) / 2,
                               reinterpret_cast<const float2*>(W), b, N);

    // 2) bucket fill
    fill_kernel<<<(E4 + 255) / 256, 256>>>(
        reinterpret_cast<const int4*>(row),
        reinterpret_cast<const int4*>(col),
        reinterpret_cast<const float4*>(norm), E4,
        row, col, norm, E);

    // 3) aggregation -> fragment-tiled A
    aggregate_kernel<<<(N + 7) / 8, 256>>>(edge_attr, N);

    // 4) GEMM + bias (HMMA)
    gemm_wmma_kernel<<<(N + GEMM_ROWS - 1) / GEMM_ROWS, 256>>>(out, N);
}

// round 13
// speedup vs baseline: 1.0112x; 1.0112x over previous
#include <cuda_runtime.h>
#include <cuda_fp16.h>
#include <mma.h>
#include <cstdint>

using namespace nvcuda;

#define N_NODES 50000
#define IN_CH   128
#define EDGE_DIM 32
#define CAT_CH  (IN_CH + EDGE_DIM)   // 160
#define OUT_CH  128
#define BUCKET_CAP 128
#define KCHUNKS (CAT_CH / 16)        // 10
#define NTILES  ((N_NODES + 15) / 16)  // 3125

// Static device scratch (no allocations allowed)
// A in fragment-native tiled layout: [tile][k-chunk][16 rows][16 cols] fp16
__device__ __align__(128) __half g_aggtile[(size_t)(NTILES + 8) * KCHUNKS * 256];
__device__ __align__(128) __half g_xh[(size_t)N_NODES * IN_CH];
__device__ __align__(128) __half g_wh[CAT_CH * OUT_CH];
__device__ __align__(16)  uint4  g_edges16[(size_t)N_NODES * BUCKET_CAP];
__device__ int g_count[N_NODES];

// ---------------------------------------------------------------------------
// Kernel 1: prep = zero(count) + x->fp16 + W->fp16
// ---------------------------------------------------------------------------
__global__ void prep_kernel(const float2* __restrict__ x2, int n2,
                            const float2* __restrict__ w2,
                            int N) {
    int i = blockIdx.x * blockDim.x + threadIdx.x;
    int stride = gridDim.x * blockDim.x;

    __half2* xdst = reinterpret_cast<__half2*>(g_xh);
    for (int k = i; k < n2; k += stride) {
        float2 v = __ldg(&x2[k]);
        xdst[k] = __float22half2_rn(v);
    }
    __half2* wdst = reinterpret_cast<__half2*>(g_wh);
    for (int k = i; k < (CAT_CH * OUT_CH) / 2; k += stride) {
        float2 v = __ldg(&w2[k]);
        wdst[k] = __float22half2_rn(v);
    }
    for (int k = i; k < N; k += stride) g_count[k] = 0;
}

// ---------------------------------------------------------------------------
// Kernel 2: bucket fill, 16B records {norm, e, col, 0}
// ---------------------------------------------------------------------------
__device__ __forceinline__ void fill_one(int r, int c, float nm, int e) {
    int pos = atomicAdd(&g_count[r], 1);
    if (pos < BUCKET_CAP) {
        g_edges16[(size_t)r * BUCKET_CAP + pos] =
            make_uint4(__float_as_uint(nm), (unsigned)e, (unsigned)c, 0u);
    }
}

__global__ void fill_kernel(const int4*   __restrict__ row4,
                            const int4*   __restrict__ col4,
                            const float4* __restrict__ norm4,
                            int E4,
                            const int* __restrict__ row,
                            const int* __restrict__ col,
                            const float* __restrict__ norm,
                            int E) {
    int i = blockIdx.x * blockDim.x + threadIdx.x;
    if (i < E4) {
        int4   r  = __ldg(&row4[i]);
        int4   c  = __ldg(&col4[i]);
        float4 nm = __ldg(&norm4[i]);
        int e = i * 4;
        fill_one(r.x, c.x, nm.x, e + 0);
        fill_one(r.y, c.y, nm.y, e + 1);
        fill_one(r.z, c.z, nm.z, e + 2);
        fill_one(r.w, c.w, nm.w, e + 3);
    }
    if (i == 0) {
        for (int t = E4 * 4; t < E; t++) fill_one(row[t], col[t], norm[t], t);
    }
}

// ---------------------------------------------------------------------------
// Kernel 3: aggregation -> fragment-tiled A (unchanged from R12)
// ---------------------------------------------------------------------------
__device__ __forceinline__ void acc_half4(float4& acc, uint2 u, float nm) {
    float2 f01 = __half22float2(*reinterpret_cast<__half2*>(&u.x));
    float2 f23 = __half22float2(*reinterpret_cast<__half2*>(&u.y));
    acc.x += nm * f01.x; acc.y += nm * f01.y;
    acc.z += nm * f23.x; acc.w += nm * f23.y;
}

__global__ void aggregate_kernel(const float* __restrict__ ea, int N) {
    int n    = (blockIdx.x * blockDim.x + threadIdx.x) >> 5;
    int lane = threadIdx.x & 31;
    if (n >= N) return;

    int cnt = __ldg(&g_count[n]);
    if (cnt > BUCKET_CAP) cnt = BUCKET_CAP;

    const uint4* bucket = g_edges16 + (size_t)n * BUCKET_CAP;
    const uint2* xh = reinterpret_cast<const uint2*>(g_xh);

    float4 acc = make_float4(0.f, 0.f, 0.f, 0.f);
    float  acce = 0.f;

    int full = cnt & ~7;
    int j = 0;
    for (; j < full; j += 8) {
        uint4 r[8];
        #pragma unroll
        for (int q = 0; q < 8; q++) r[q] = __ldg(&bucket[j + q]);
        uint2 u[8];
        #pragma unroll
        for (int q = 0; q < 8; q++)
            u[q] = __ldg(&xh[r[q].z * (IN_CH / 4) + (unsigned)lane]);
        float g[8];
        #pragma unroll
        for (int q = 0; q < 8; q++)
            g[q] = __ldg(&ea[(size_t)r[q].y * EDGE_DIM + lane]);
        #pragma unroll
        for (int q = 0; q < 8; q++) {
            float w = __uint_as_float(r[q].x);
            acc_half4(acc, u[q], w);
            acce += w * g[q];
        }
    }
    if (j < cnt) {
        uint4 r[8];
        float w[8];
        #pragma unroll
        for (int q = 0; q < 8; q++) {
            int idx  = j + q;
            int slot = (idx < cnt) ? idx : 0;
            r[q] = __ldg(&bucket[slot]);
            w[q] = (idx < cnt) ? __uint_as_float(r[q].x) : 0.f;
        }
        uint2 u[8];
        #pragma unroll
        for (int q = 0; q < 8; q++)
            u[q] = __ldg(&xh[r[q].z * (IN_CH / 4) + (unsigned)lane]);
        float g[8];
        #pragma unroll
        for (int q = 0; q < 8; q++)
            g[q] = __ldg(&ea[(size_t)r[q].y * EDGE_DIM + lane]);
        #pragma unroll
        for (int q = 0; q < 8; q++) {
            acc_half4(acc, u[q], w[q]);
            acce += w[q] * g[q];
        }
    }

    int t  = n >> 4;
    int rr = n & 15;
    __half* base = g_aggtile + (size_t)t * (KCHUNKS * 256);

    __half2 h01 = __floats2half2_rn(acc.x, acc.y);
    __half2 h23 = __floats2half2_rn(acc.z, acc.w);
    uint2 st;
    st.x = *reinterpret_cast<uint32_t*>(&h01);
    st.y = *reinterpret_cast<uint32_t*>(&h23);
    *reinterpret_cast<uint2*>(base + (lane >> 2) * 256 + rr * 16 + (lane & 3) * 4) = st;
    base[(8 + (lane >> 4)) * 256 + rr * 16 + (lane & 15)] = __float2half_rn(acce);
}

// ---------------------------------------------------------------------------
// Kernel 4: GEMM. W in smem; A tiled-global fragments; ZERO-init accumulators;
// epilogue: frags -> padded smem C -> coalesced bias-add STG.128.
// ---------------------------------------------------------------------------
#define GEMM_ROWS 64
#define C_LD 132                                  // padded f32 row stride
#define SW_BYTES (CAT_CH * OUT_CH * 2)            // 40960
#define SC_BYTES (GEMM_ROWS * C_LD * 4)           // 33792
#define GEMM_SMEM (SW_BYTES + SC_BYTES)           // 74752

__global__ void gemm_wmma_kernel(const float* __restrict__ b,
                                 float* __restrict__ out, int N) {
    extern __shared__ char smem[];
    __half* sW = reinterpret_cast<__half*>(smem);
    float*  sC = reinterpret_cast<float*>(smem + SW_BYTES);

    int tid = threadIdx.x;
    {
        const uint4* src = reinterpret_cast<const uint4*>(g_wh);
        uint4* dst = reinterpret_cast<uint4*>(sW);
        #pragma unroll
        for (int i = tid; i < SW_BYTES / 16; i += 256) dst[i] = src[i];
    }
    __syncthreads();

    int wid = tid >> 5;
    int mi = wid & 3;
    int ng = wid >> 2;

    int rowBase = blockIdx.x * GEMM_ROWS + mi * 16;
    bool valid = (rowBase < N);                   // N % 16 == 0

    if (valid) {
        int tile = rowBase >> 4;
        const __half* A = g_aggtile + (size_t)tile * (KCHUNKS * 256);
        const __half* Wp = sW + ng * 64;

        wmma::fragment<wmma::accumulator, 16, 16, 16, float> acc[4];
        #pragma unroll
        for (int f = 0; f < 4; f++) wmma::fill_fragment(acc[f], 0.0f);

        #pragma unroll
        for (int k = 0; k < KCHUNKS; k++) {
            wmma::fragment<wmma::matrix_a, 16, 16, 16, __half, wmma::row_major> a;
            wmma::load_matrix_sync(a, A + k * 256, 16);
            #pragma unroll
            for (int f = 0; f < 4; f++) {
                wmma::fragment<wmma::matrix_b, 16, 16, 16, __half, wmma::row_major> bb;
                wmma::load_matrix_sync(bb, Wp + k * 16 * OUT_CH + f * 16, OUT_CH);
                wmma::mma_sync(acc[f], a, bb, acc[f]);
            }
        }

        float* cdst = sC + mi * 16 * C_LD + ng * 64;
        #pragma unroll
        for (int f = 0; f < 4; f++)
            wmma::store_matrix_sync(cdst + f * 16, acc[f], C_LD, wmma::mem_row_major);
    }
    __syncthreads();

    // Epilogue: warp-per-row coalesced bias-add stores.
    int lane = tid & 31;
    int wrow = tid >> 5;                          // warp id -> row within pass
    float4 bias = __ldg(reinterpret_cast<const float4*>(b) + lane);
    int blockRow0 = blockIdx.x * GEMM_ROWS;
    #pragma unroll
    for (int p = 0; p < 8; p++) {
        int r = p * 8 + wrow;
        int grow = blockRow0 + r;
        if (grow < N) {
            float4 v = *reinterpret_cast<const float4*>(sC + r * C_LD + lane * 4);
            v.x += bias.x; v.y += bias.y; v.z += bias.z; v.w += bias.w;
            reinterpret_cast<float4*>(out + (size_t)grow * OUT_CH)[lane] = v;
        }
    }
}

// ---------------------------------------------------------------------------
// Launch: 4 kernels, single stream. (4th = gemm = profiled slot)
// ---------------------------------------------------------------------------
extern "C" void kernel_launch(void* const* d_in, const int* in_sizes, int n_in,
                              void* d_out, int out_size) {
    const float* x         = (const float*)d_in[0];
    const int*   row       = (const int*)  d_in[1];
    const int*   col       = (const int*)  d_in[2];
    const float* norm      = (const float*)d_in[3];
    const float* edge_attr = (const float*)d_in[4];
    const float* W         = (const float*)d_in[5];
    const float* b         = (const float*)d_in[6];
    float* out = (float*)d_out;

    int N = in_sizes[0] / IN_CH;
    int E = in_sizes[1];
    int E4 = E / 4;

    static bool init = false;
    if (!init) {
        cudaFuncSetAttribute(gemm_wmma_kernel,
                             cudaFuncAttributeMaxDynamicSharedMemorySize, GEMM_SMEM);
        init = true;
    }

    // 1) prep
    prep_kernel<<<2048, 512>>>(reinterpret_cast<const float2*>(x),
                               (N * IN_CH) / 2,
                               reinterpret_cast<const float2*>(W), N);

    // 2) bucket fill
    fill_kernel<<<(E4 + 255) / 256, 256>>>(
        reinterpret_cast<const int4*>(row),
        reinterpret_cast<const int4*>(col),
        reinterpret_cast<const float4*>(norm), E4,
        row, col, norm, E);

    // 3) aggregation -> fragment-tiled A
    aggregate_kernel<<<(N + 7) / 8, 256>>>(edge_attr, N);

    // 4) GEMM + bias (HMMA, smem epilogue)
    gemm_wmma_kernel<<<(N + GEMM_ROWS - 1) / GEMM_ROWS, 256, GEMM_SMEM>>>(b, out, N);
}

// round 14
// speedup vs baseline: 1.1492x; 1.1365x over previous
#include <cuda_runtime.h>
#include <cuda_fp16.h>
#include <mma.h>
#include <cstdint>

using namespace nvcuda;

#define N_NODES 50000
#define IN_CH   128
#define EDGE_DIM 32
#define CAT_CH  (IN_CH + EDGE_DIM)   // 160
#define OUT_CH  128
#define BUCKET_CAP 128
#define KCHUNKS (CAT_CH / 16)        // 10
#define NTILES_N ((N_NODES + 15) / 16)  // 3125

// Static device scratch (no allocations allowed)
// A in fragment-native tiled layout: [tile][k-chunk][16 rows][16 cols] fp16
__device__ __align__(128) __half g_aggtile[(size_t)(NTILES_N + 8) * KCHUNKS * 256];
__device__ __align__(128) __half g_xh[(size_t)N_NODES * IN_CH];
// W in fragment-tiled layout: [kchunk][ntile(8)][16][16] fp16
__device__ __align__(128) __half g_wt[KCHUNKS * 8 * 256];
__device__ __align__(16)  uint4  g_edges16[(size_t)N_NODES * BUCKET_CAP];
__device__ int g_count[N_NODES];

// ---------------------------------------------------------------------------
// Kernel 1: prep = zero(count) + x->fp16 + W->fp16 fragment-tiled
// ---------------------------------------------------------------------------
__global__ void prep_kernel(const float2* __restrict__ x2, int n2,
                            const float* __restrict__ w,
                            int N) {
    int i = blockIdx.x * blockDim.x + threadIdx.x;
    int stride = gridDim.x * blockDim.x;

    __half2* xdst = reinterpret_cast<__half2*>(g_xh);
    for (int k = i; k < n2; k += stride) {
        float2 v = __ldg(&x2[k]);
        xdst[k] = __float22half2_rn(v);
    }
    // W [160][128] row-major -> tiled [k][nt][r][c]
    for (int k = i; k < CAT_CH * OUT_CH; k += stride) {
        int kr = k >> 7;          // k-row 0..159
        int nc = k & 127;         // n-col 0..127
        int dst = ((kr >> 4) * 8 + (nc >> 4)) * 256 + (kr & 15) * 16 + (nc & 15);
        g_wt[dst] = __float2half_rn(__ldg(&w[k]));
    }
    for (int k = i; k < N; k += stride) g_count[k] = 0;
}

// ---------------------------------------------------------------------------
// Kernel 2: bucket fill, 16B records {norm, e, col, 0}
// ---------------------------------------------------------------------------
__device__ __forceinline__ void fill_one(int r, int c, float nm, int e) {
    int pos = atomicAdd(&g_count[r], 1);
    if (pos < BUCKET_CAP) {
        g_edges16[(size_t)r * BUCKET_CAP + pos] =
            make_uint4(__float_as_uint(nm), (unsigned)e, (unsigned)c, 0u);
    }
}

__global__ void fill_kernel(const int4*   __restrict__ row4,
                            const int4*   __restrict__ col4,
                            const float4* __restrict__ norm4,
                            int E4,
                            const int* __restrict__ row,
                            const int* __restrict__ col,
                            const float* __restrict__ norm,
                            int E) {
    int i = blockIdx.x * blockDim.x + threadIdx.x;
    if (i < E4) {
        int4   r  = __ldg(&row4[i]);
        int4   c  = __ldg(&col4[i]);
        float4 nm = __ldg(&norm4[i]);
        int e = i * 4;
        fill_one(r.x, c.x, nm.x, e + 0);
        fill_one(r.y, c.y, nm.y, e + 1);
        fill_one(r.z, c.z, nm.z, e + 2);
        fill_one(r.w, c.w, nm.w, e + 3);
    }
    if (i == 0) {
        for (int t = E4 * 4; t < E; t++) fill_one(row[t], col[t], norm[t], t);
    }
}

// ---------------------------------------------------------------------------
// Kernel 3: aggregation -> fragment-tiled A (unchanged)
// ---------------------------------------------------------------------------
__device__ __forceinline__ void acc_half4(float4& acc, uint2 u, float nm) {
    float2 f01 = __half22float2(*reinterpret_cast<__half2*>(&u.x));
    float2 f23 = __half22float2(*reinterpret_cast<__half2*>(&u.y));
    acc.x += nm * f01.x; acc.y += nm * f01.y;
    acc.z += nm * f23.x; acc.w += nm * f23.y;
}

__global__ void aggregate_kernel(const float* __restrict__ ea, int N) {
    int n    = (blockIdx.x * blockDim.x + threadIdx.x) >> 5;
    int lane = threadIdx.x & 31;
    if (n >= N) return;

    int cnt = __ldg(&g_count[n]);
    if (cnt > BUCKET_CAP) cnt = BUCKET_CAP;

    const uint4* bucket = g_edges16 + (size_t)n * BUCKET_CAP;
    const uint2* xh = reinterpret_cast<const uint2*>(g_xh);

    float4 acc = make_float4(0.f, 0.f, 0.f, 0.f);
    float  acce = 0.f;

    int full = cnt & ~7;
    int j = 0;
    for (; j < full; j += 8) {
        uint4 r[8];
        #pragma unroll
        for (int q = 0; q < 8; q++) r[q] = __ldg(&bucket[j + q]);
        uint2 u[8];
        #pragma unroll
        for (int q = 0; q < 8; q++)
            u[q] = __ldg(&xh[r[q].z * (IN_CH / 4) + (unsigned)lane]);
        float g[8];
        #pragma unroll
        for (int q = 0; q < 8; q++)
            g[q] = __ldg(&ea[(size_t)r[q].y * EDGE_DIM + lane]);
        #pragma unroll
        for (int q = 0; q < 8; q++) {
            float w = __uint_as_float(r[q].x);
            acc_half4(acc, u[q], w);
            acce += w * g[q];
        }
    }
    if (j < cnt) {
        uint4 r[8];
        float w[8];
        #pragma unroll
        for (int q = 0; q < 8; q++) {
            int idx  = j + q;
            int slot = (idx < cnt) ? idx : 0;
            r[q] = __ldg(&bucket[slot]);
            w[q] = (idx < cnt) ? __uint_as_float(r[q].x) : 0.f;
        }
        uint2 u[8];
        #pragma unroll
        for (int q = 0; q < 8; q++)
            u[q] = __ldg(&xh[r[q].z * (IN_CH / 4) + (unsigned)lane]);
        float g[8];
        #pragma unroll
        for (int q = 0; q < 8; q++)
            g[q] = __ldg(&ea[(size_t)r[q].y * EDGE_DIM + lane]);
        #pragma unroll
        for (int q = 0; q < 8; q++) {
            acc_half4(acc, u[q], w[q]);
            acce += w[q] * g[q];
        }
    }

    int t  = n >> 4;
    int rr = n & 15;
    __half* base = g_aggtile + (size_t)t * (KCHUNKS * 256);

    __half2 h01 = __floats2half2_rn(acc.x, acc.y);
    __half2 h23 = __floats2half2_rn(acc.z, acc.w);
    uint2 st;
    st.x = *reinterpret_cast<uint32_t*>(&h01);
    st.y = *reinterpret_cast<uint32_t*>(&h23);
    *reinterpret_cast<uint2*>(base + (lane >> 2) * 256 + rr * 16 + (lane & 3) * 4) = st;
    base[(8 + (lane >> 4)) * 256 + rr * 16 + (lane & 15)] = __float2half_rn(acce);
}

// ---------------------------------------------------------------------------
// Kernel 4: persistent GEMM, W fragments in REGISTERS (loaded once/block).
// 8 warps = 2 m-tiles x 4 n-groups (32 cols). 32-row groups, smem epilogue.
// ---------------------------------------------------------------------------
#define C_LD 132
#define SC_WORDS (32 * C_LD)       // 4224 f32 = 16.5 KB

__global__ void __launch_bounds__(256, 2)
gemm_wmma_kernel(const float* __restrict__ b,
                 float* __restrict__ out, int N, int ngroups) {
    __shared__ float sC[SC_WORDS];

    int tid = threadIdx.x;
    int wid = tid >> 5;
    int lane = tid & 31;
    int mi = wid & 1;      // m-tile within 32-row group
    int ng = wid >> 1;     // n-group: cols [ng*32, ng*32+32)

    // Load this warp's 20 W fragments into registers (once).
    wmma::fragment<wmma::matrix_b, 16, 16, 16, __half, wmma::row_major> wf[KCHUNKS][2];
    #pragma unroll
    for (int k = 0; k < KCHUNKS; k++) {
        #pragma unroll
        for (int f = 0; f < 2; f++) {
            wmma::load_matrix_sync(wf[k][f],
                g_wt + ((size_t)k * 8 + (ng * 2 + f)) * 256, 16);
        }
    }

    float4 bias = __ldg(reinterpret_cast<const float4*>(b) + lane);

    for (int g = blockIdx.x; g < ngroups; g += gridDim.x) {
        int tile = g * 2 + mi;
        const __half* A = g_aggtile + (size_t)tile * (KCHUNKS * 256);

        wmma::fragment<wmma::accumulator, 16, 16, 16, float> acc[2];
        wmma::fill_fragment(acc[0], 0.0f);
        wmma::fill_fragment(acc[1], 0.0f);

        #pragma unroll
        for (int k = 0; k < KCHUNKS; k++) {
            wmma::fragment<wmma::matrix_a, 16, 16, 16, __half, wmma::row_major> a;
            wmma::load_matrix_sync(a, A + k * 256, 16);   // contiguous 512 B
            wmma::mma_sync(acc[0], a, wf[k][0], acc[0]);
            wmma::mma_sync(acc[1], a, wf[k][1], acc[1]);
        }

        float* cd = sC + mi * 16 * C_LD + ng * 32;
        wmma::store_matrix_sync(cd,      acc[0], C_LD, wmma::mem_row_major);
        wmma::store_matrix_sync(cd + 16, acc[1], C_LD, wmma::mem_row_major);
        __syncthreads();

        // coalesced bias-add stores: warp wid handles rows wid, wid+8, ...
        int row0 = g * 32;
        #pragma unroll
        for (int p = 0; p < 4; p++) {
            int r = p * 8 + wid;
            int grow = row0 + r;
            if (grow < N) {
                float4 v = *reinterpret_cast<const float4*>(sC + r * C_LD + lane * 4);
                v.x += bias.x; v.y += bias.y; v.z += bias.z; v.w += bias.w;
                reinterpret_cast<float4*>(out + (size_t)grow * OUT_CH)[lane] = v;
            }
        }
        __syncthreads();
    }
}

// ---------------------------------------------------------------------------
// Launch: 4 kernels, single stream. (4th = gemm = profiled slot)
// ---------------------------------------------------------------------------
extern "C" void kernel_launch(void* const* d_in, const int* in_sizes, int n_in,
                              void* d_out, int out_size) {
    const float* x         = (const float*)d_in[0];
    const int*   row       = (const int*)  d_in[1];
    const int*   col       = (const int*)  d_in[2];
    const float* norm      = (const float*)d_in[3];
    const float* edge_attr = (const float*)d_in[4];
    const float* W         = (const float*)d_in[5];
    const float* b         = (const float*)d_in[6];
    float* out = (float*)d_out;

    int N = in_sizes[0] / IN_CH;
    int E = in_sizes[1];
    int E4 = E / 4;
    int ngroups = (N + 31) / 32;

    // 1) prep
    prep_kernel<<<2048, 512>>>(reinterpret_cast<const float2*>(x),
                               (N * IN_CH) / 2, W, N);

    // 2) bucket fill
    fill_kernel<<<(E4 + 255) / 256, 256>>>(
        reinterpret_cast<const int4*>(row),
        reinterpret_cast<const int4*>(col),
        reinterpret_cast<const float4*>(norm), E4,
        row, col, norm, E);

    // 3) aggregation -> fragment-tiled A
    aggregate_kernel<<<(N + 7) / 8, 256>>>(edge_attr, N);

    // 4) persistent GEMM + bias (HMMA, register W)
    gemm_wmma_kernel<<<592, 256>>>(b, out, N, ngroups);
}

// round 15
// speedup vs baseline: 1.4097x; 1.2266x over previous
#include <cuda_runtime.h>
#include <cuda_fp16.h>
#include <mma.h>
#include <cstdint>

using namespace nvcuda;

#define N_NODES 50000
#define IN_CH   128
#define EDGE_DIM 32
#define CAT_CH  (IN_CH + EDGE_DIM)   // 160
#define OUT_CH  128
#define BUCKET_CAP 128
#define KCHUNKS (CAT_CH / 16)        // 10
#define NTILES_N ((N_NODES + 15) / 16)  // 3125

// Static device scratch (no allocations allowed)
__device__ __align__(128) __half g_aggtile[(size_t)(NTILES_N + 8) * KCHUNKS * 256];
__device__ __align__(128) __half g_xh[(size_t)N_NODES * IN_CH];
__device__ __align__(128) __half g_wt[KCHUNKS * 8 * 256];   // W tiled [k][nt][16][16]
__device__ __align__(16)  uint2  g_edges8[(size_t)N_NODES * BUCKET_CAP]; // 51 MB
__device__ int g_count[N_NODES];

// ---------------------------------------------------------------------------
// Kernel 1: x -> fp16
// ---------------------------------------------------------------------------
__global__ void prep_x_kernel(const float2* __restrict__ x2, int n2) {
    __half2* xdst = reinterpret_cast<__half2*>(g_xh);
    int i = blockIdx.x * blockDim.x + threadIdx.x;
    int stride = gridDim.x * blockDim.x;
    for (; i < n2; i += stride) {
        float2 v = __ldg(&x2[i]);
        xdst[i] = __float22half2_rn(v);
    }
}

// ---------------------------------------------------------------------------
// Kernel 2: W -> fp16 fragment-tiled + zero counts
// ---------------------------------------------------------------------------
__global__ void prep_w_kernel(const float* __restrict__ w, int N) {
    int i = blockIdx.x * blockDim.x + threadIdx.x;
    int stride = gridDim.x * blockDim.x;
    for (int k = i; k < CAT_CH * OUT_CH; k += stride) {
        int kr = k >> 7;          // k-row 0..159
        int nc = k & 127;         // n-col 0..127
        int dst = ((kr >> 4) * 8 + (nc >> 4)) * 256 + (kr & 15) * 16 + (nc & 15);
        g_wt[dst] = __float2half_rn(__ldg(&w[k]));
    }
    for (int k = i; k < N; k += stride) g_count[k] = 0;
}

// ---------------------------------------------------------------------------
// Kernel 3: bucket fill, 8B records {col<<16 | norm_fp16, e}
// ---------------------------------------------------------------------------
__device__ __forceinline__ void fill_one(int r, int c, float nm, int e) {
    int pos = atomicAdd(&g_count[r], 1);
    if (pos < BUCKET_CAP) {
        unsigned hb = __half_as_ushort(__float2half_rn(nm));
        g_edges8[(size_t)r * BUCKET_CAP + pos] =
            make_uint2(((unsigned)c << 16) | hb, (unsigned)e);
    }
}

__global__ void fill_kernel(const int4*   __restrict__ row4,
                            const int4*   __restrict__ col4,
                            const float4* __restrict__ norm4,
                            int E4,
                            const int* __restrict__ row,
                            const int* __restrict__ col,
                            const float* __restrict__ norm,
                            int E) {
    int i = blockIdx.x * blockDim.x + threadIdx.x;
    if (i < E4) {
        int4   r  = __ldg(&row4[i]);
        int4   c  = __ldg(&col4[i]);
        float4 nm = __ldg(&norm4[i]);
        int e = i * 4;
        fill_one(r.x, c.x, nm.x, e + 0);
        fill_one(r.y, c.y, nm.y, e + 1);
        fill_one(r.z, c.z, nm.z, e + 2);
        fill_one(r.w, c.w, nm.w, e + 3);
    }
    if (i == 0) {
        for (int t = E4 * 4; t < E; t++) fill_one(row[t], col[t], norm[t], t);
    }
}

// ---------------------------------------------------------------------------
// Kernel 4 (PROFILED): aggregation -> fragment-tiled A.
// One warp per node. 8B records; x fp16 gather (8B/lane), ea fp32 gather
// (4B/lane, 128B/warp contiguous). fp32 accumulate.
// ---------------------------------------------------------------------------
__device__ __forceinline__ void acc_half4(float4& acc, uint2 u, float nm) {
    float2 f01 = __half22float2(*reinterpret_cast<__half2*>(&u.x));
    float2 f23 = __half22float2(*reinterpret_cast<__half2*>(&u.y));
    acc.x += nm * f01.x; acc.y += nm * f01.y;
    acc.z += nm * f23.x; acc.w += nm * f23.y;
}

__global__ void aggregate_kernel(const float* __restrict__ ea, int N) {
    int n    = (blockIdx.x * blockDim.x + threadIdx.x) >> 5;
    int lane = threadIdx.x & 31;
    if (n >= N) return;

    int cnt = __ldg(&g_count[n]);
    if (cnt > BUCKET_CAP) cnt = BUCKET_CAP;

    const uint2* bucket = g_edges8 + (size_t)n * BUCKET_CAP;
    const uint2* xh = reinterpret_cast<const uint2*>(g_xh);

    float4 acc = make_float4(0.f, 0.f, 0.f, 0.f);
    float  acce = 0.f;

    int full = cnt & ~7;
    int j = 0;
    for (; j < full; j += 8) {
        uint2 r[8];
        #pragma unroll
        for (int q = 0; q < 8; q++) r[q] = __ldg(&bucket[j + q]);
        uint2 u[8];
        #pragma unroll
        for (int q = 0; q < 8; q++)
            u[q] = __ldg(&xh[(r[q].x >> 16) * (IN_CH / 4) + (unsigned)lane]);
        float g[8];
        #pragma unroll
        for (int q = 0; q < 8; q++)
            g[q] = __ldg(&ea[(size_t)r[q].y * EDGE_DIM + lane]);
        #pragma unroll
        for (int q = 0; q < 8; q++) {
            float w = __half2float(__ushort_as_half((unsigned short)(r[q].x & 0xFFFF)));
            acc_half4(acc, u[q], w);
            acce += w * g[q];
        }
    }
    if (j < cnt) {
        uint2 r[8];
        float w[8];
        #pragma unroll
        for (int q = 0; q < 8; q++) {
            int idx  = j + q;
            int slot = (idx < cnt) ? idx : 0;
            r[q] = __ldg(&bucket[slot]);
            w[q] = (idx < cnt)
                 ? __half2float(__ushort_as_half((unsigned short)(r[q].x & 0xFFFF)))
                 : 0.f;
        }
        uint2 u[8];
        #pragma unroll
        for (int q = 0; q < 8; q++)
            u[q] = __ldg(&xh[(r[q].x >> 16) * (IN_CH / 4) + (unsigned)lane]);
        float g[8];
        #pragma unroll
        for (int q = 0; q < 8; q++)
            g[q] = __ldg(&ea[(size_t)r[q].y * EDGE_DIM + lane]);
        #pragma unroll
        for (int q = 0; q < 8; q++) {
            acc_half4(acc, u[q], w[q]);
            acce += w[q] * g[q];
        }
    }

    int t  = n >> 4;
    int rr = n & 15;
    __half* base = g_aggtile + (size_t)t * (KCHUNKS * 256);

    __half2 h01 = __floats2half2_rn(acc.x, acc.y);
    __half2 h23 = __floats2half2_rn(acc.z, acc.w);
    uint2 st;
    st.x = *reinterpret_cast<uint32_t*>(&h01);
    st.y = *reinterpret_cast<uint32_t*>(&h23);
    *reinterpret_cast<uint2*>(base + (lane >> 2) * 256 + rr * 16 + (lane & 3) * 4) = st;
    base[(8 + (lane >> 4)) * 256 + rr * 16 + (lane & 15)] = __float2half_rn(acce);
}

// ---------------------------------------------------------------------------
// Kernel 5: persistent GEMM, register-resident W fragments (unchanged R14).
// ---------------------------------------------------------------------------
#define C_LD 132
#define SC_WORDS (32 * C_LD)

__global__ void __launch_bounds__(256, 2)
gemm_wmma_kernel(const float* __restrict__ b,
                 float* __restrict__ out, int N, int ngroups) {
    __shared__ float sC[SC_WORDS];

    int tid = threadIdx.x;
    int wid = tid >> 5;
    int lane = tid & 31;
    int mi = wid & 1;
    int ng = wid >> 1;

    wmma::fragment<wmma::matrix_b, 16, 16, 16, __half, wmma::row_major> wf[KCHUNKS][2];
    #pragma unroll
    for (int k = 0; k < KCHUNKS; k++) {
        #pragma unroll
        for (int f = 0; f < 2; f++) {
            wmma::load_matrix_sync(wf[k][f],
                g_wt + ((size_t)k * 8 + (ng * 2 + f)) * 256, 16);
        }
    }

    float4 bias = __ldg(reinterpret_cast<const float4*>(b) + lane);

    for (int g = blockIdx.x; g < ngroups; g += gridDim.x) {
        int tile = g * 2 + mi;
        const __half* A = g_aggtile + (size_t)tile * (KCHUNKS * 256);

        wmma::fragment<wmma::accumulator, 16, 16, 16, float> acc[2];
        wmma::fill_fragment(acc[0], 0.0f);
        wmma::fill_fragment(acc[1], 0.0f);

        #pragma unroll
        for (int k = 0; k < KCHUNKS; k++) {
            wmma::fragment<wmma::matrix_a, 16, 16, 16, __half, wmma::row_major> a;
            wmma::load_matrix_sync(a, A + k * 256, 16);
            wmma::mma_sync(acc[0], a, wf[k][0], acc[0]);
            wmma::mma_sync(acc[1], a, wf[k][1], acc[1]);
        }

        float* cd = sC + mi * 16 * C_LD + ng * 32;
        wmma::store_matrix_sync(cd,      acc[0], C_LD, wmma::mem_row_major);
        wmma::store_matrix_sync(cd + 16, acc[1], C_LD, wmma::mem_row_major);
        __syncthreads();

        int row0 = g * 32;
        #pragma unroll
        for (int p = 0; p < 4; p++) {
            int r = p * 8 + wid;
            int grow = row0 + r;
            if (grow < N) {
                float4 v = *reinterpret_cast<const float4*>(sC + r * C_LD + lane * 4);
                v.x += bias.x; v.y += bias.y; v.z += bias.z; v.w += bias.w;
                reinterpret_cast<float4*>(out + (size_t)grow * OUT_CH)[lane] = v;
            }
        }
        __syncthreads();
    }
}

// ---------------------------------------------------------------------------
// Launch: 5 kernels; aggregate is the 4th launch (profiled slot).
// ---------------------------------------------------------------------------
extern "C" void kernel_launch(void* const* d_in, const int* in_sizes, int n_in,
                              void* d_out, int out_size) {
    const float* x         = (const float*)d_in[0];
    const int*   row       = (const int*)  d_in[1];
    const int*   col       = (const int*)  d_in[2];
    const float* norm      = (const float*)d_in[3];
    const float* edge_attr = (const float*)d_in[4];
    const float* W         = (const float*)d_in[5];
    const float* b         = (const float*)d_in[6];
    float* out = (float*)d_out;

    int N = in_sizes[0] / IN_CH;
    int E = in_sizes[1];
    int E4 = E / 4;
    int ngroups = (N + 31) / 32;

    // 1) x -> fp16
    prep_x_kernel<<<2048, 512>>>(reinterpret_cast<const float2*>(x), (N * IN_CH) / 2);

    // 2) W tile + zero counts
    prep_w_kernel<<<256, 256>>>(W, N);

    // 3) bucket fill (8B records)
    fill_kernel<<<(E4 + 255) / 256, 256>>>(
        reinterpret_cast<const int4*>(row),
        reinterpret_cast<const int4*>(col),
        reinterpret_cast<const float4*>(norm), E4,
        row, col, norm, E);

    // 4) aggregation -> fragment-tiled A   [profiled]
    aggregate_kernel<<<(N + 7) / 8, 256>>>(edge_attr, N);

    // 5) persistent GEMM + bias
    gemm_wmma_kernel<<<592, 256>>>(b, out, N, ngroups);
}